// round 2
// baseline (speedup 1.0000x reference)
#include <cuda_runtime.h>
#include <cuda_bf16.h>
#include <stdint.h>

// PositionEncoding: out[pos][64] = is_class ? E_class[cid[pos]] : sincos(values[pos])
// sincos dim 2i = sin(2^i * pi * v), 2i+1 = cos(2^i * pi * v). The fp32 angle in the
// reference is EXACTLY ang_i = 2^i * fl(v * pi_f) (power-of-2 scaling is exact).
//
// 16 threads per position; thread owns one 16B chunk (levels 2k, 2k+1).
//   - u = theta/(2pi) as 64-bit fixed point: integer multiply by
//     Q = floor(2^64/(2pi)) = 0x28BE60DB9391054A (Payne-Hanek bits).
//   - frac(2^l * u) = (u << l); top 32 bits signed -> angle in [-pi, pi).
//   - MUFU sin/cos at even level, one double-angle step for the odd level.
//   - float4 stores, fully coalesced.

#define NPOS      (64 * 8192)      // B * S
#define NTHREADS  (NPOS * 16)

__global__ __launch_bounds__(256)
void pe_kernel(const float*  __restrict__ values,
               const float4* __restrict__ E,        // [4096][16] float4
               const int*    __restrict__ cid,
               const int*    __restrict__ isc,
               float4*       __restrict__ out)      // [NPOS][16] float4
{
    const int t     = blockIdx.x * blockDim.x + threadIdx.x;
    const int pos   = t >> 4;
    const int chunk = t & 15;

    float4 r;
    if (__ldg(&isc[pos]) != 0) {
        // class embedding gather: 16 lanes cover the 256B row -> coalesced, L2-resident
        r = __ldg(&E[(size_t)__ldg(&cid[pos]) * 16 + chunk]);
    } else {
        const float v  = __ldg(&values[pos]);
        // theta = fl(v * pi_f), pi_f = 0x40490FDB
        const float th = v * __uint_as_float(0x40490FDBu);

        // ---- u = frac(theta / (2pi)) in 64-bit fixed point ----
        const uint32_t b = __float_as_uint(th);        // th >= 0
        const uint32_t e = b >> 23;                    // biased exponent (<= 128)
        const uint32_t m = (b & 0x7FFFFFu) | (e ? 0x800000u : 0u);
        // theta = m * 2^(e-150); Q = 0x28BE60DB_9391054A
        const uint64_t p1 = (uint64_t)m * 0x9391054AULL;   // m * Q_lo  (< 2^56)
        const uint64_t p2 = (uint64_t)m * 0x28BE60DBULL;   // m * Q_hi  (< 2^54)
        const uint64_t U0 = (p2 << 10) + (p1 >> 22);       // (m*Q) >> 22, fits 64b
        const uint32_t sh = 128u - e;
        const uint64_t u  = (sh < 64u) ? (U0 >> sh) : 0ULL; // u64 < 2^63 (theta < pi)

        // ---- anchor at level l = 2*chunk ----
        const int      lvl = chunk << 1;
        const uint64_t f   = u << lvl;                 // frac(2^l*u) * 2^64
        const int32_t  ti  = (int32_t)(f >> 32);       // signed -> [-0.5, 0.5) cycles
        const float    ang = (float)ti * 1.4629180792671596e-9f;  // * 2pi / 2^32
        const float s0 = __sinf(ang);
        const float c0 = __cosf(ang);

        // ---- one double-angle step for level l+1 ----
        const float t2 = c0 + c0;
        const float c1 = fmaf(t2, c0, -1.0f);          // cos(2a) = 2c^2 - 1
        const float s1 = t2 * s0;                      // sin(2a) = 2sc

        r = make_float4(s0, c0, s1, c1);
    }

    out[(size_t)pos * 16 + chunk] = r;
}

extern "C" void kernel_launch(void* const* d_in, const int* in_sizes, int n_in,
                              void* d_out, int out_size)
{
    const float*  values = (const float*)d_in[0];
    const float4* E      = (const float4*)d_in[1];
    const int*    cids   = (const int*)d_in[2];
    const int*    isc    = (const int*)d_in[3];
    float4*       out    = (float4*)d_out;

    const int threads = 256;
    const int blocks  = NTHREADS / threads;   // 32768
    pe_kernel<<<blocks, threads>>>(values, E, cids, isc, out);
}

// round 6
// speedup vs baseline: 1.6033x; 1.6033x over previous
#include <cuda_runtime.h>
#include <cuda_bf16.h>
#include <stdint.h>

// PositionEncoding: out[pos][64] = is_class ? E_class[cid[pos]] : sincos(values[pos])
// sincos dim 2i = sin(2^i*pi*v), 2i+1 = cos(2^i*pi*v); fp32 angle is exactly
// 2^i * fl(v*pi_f) (power-of-2 scaling exact) -> 64-bit fixed-point reduction.
//
// Latency-bound fix (R2-R5): 4 positions per thread; all scalar loads
// front-loaded (MLP~16), unconditional E gather (cid always in [0,4096)),
// branchless select. Stores perfectly coalesced float4.

#define NPOS      (64 * 8192)            // B * S
#define NTHREADS  (NPOS * 16)
#define UNROLL    4
#define GSIZE     (NTHREADS / UNROLL)    // 2,097,152 (divisible by 16)
#define PSTRIDE   (GSIZE / 16)           // position stride between iters

__global__ __launch_bounds__(256)
void pe_kernel(const float*  __restrict__ values,
               const float4* __restrict__ E,        // [4096][16] float4
               const int*    __restrict__ cid,
               const int*    __restrict__ isc,
               float4*       __restrict__ out)      // [NPOS][16] float4
{
    const int g       = blockIdx.x * blockDim.x + threadIdx.x;
    const int chunk   = g & 15;          // same chunk all iters (GSIZE % 16 == 0)
    const int lvl     = chunk << 1;
    const int posBase = g >> 4;

    int   iv [UNROLL];
    float vv [UNROLL];
    int   cv [UNROLL];

    // ---- phase 1: all independent scalar loads in flight ----
    #pragma unroll
    for (int i = 0; i < UNROLL; i++) {
        const int p = posBase + i * PSTRIDE;
        iv[i] = __ldg(&isc[p]);
        vv[i] = __ldg(&values[p]);
        cv[i] = __ldg(&cid[p]);
    }

    // ---- phase 2: unconditional E gathers (L2-resident, 16 lanes = 256B row) ----
    float4 e[UNROLL];
    #pragma unroll
    for (int i = 0; i < UNROLL; i++)
        e[i] = __ldg(&E[(size_t)cv[i] * 16 + chunk]);

    // ---- phase 3: sincos + branchless select ----
    float4 r[UNROLL];
    #pragma unroll
    for (int i = 0; i < UNROLL; i++) {
        // theta = fl(v * pi_f), pi_f = 0x40490FDB
        const float th = vv[i] * __uint_as_float(0x40490FDBu);

        // u = frac(theta/(2pi)) in 64-bit fixed point, Q = floor(2^64/(2pi))
        const uint32_t b  = __float_as_uint(th);         // th >= 0
        const uint32_t ex = b >> 23;                     // biased exponent (<=128)
        const uint32_t m  = (b & 0x7FFFFFu) | (ex ? 0x800000u : 0u);
        const uint64_t p1 = (uint64_t)m * 0x9391054AULL; // m*Q_lo  (< 2^56)
        const uint64_t p2 = (uint64_t)m * 0x28BE60DBULL; // m*Q_hi  (< 2^54)
        const uint64_t U0 = (p2 << 10) + (p1 >> 22);     // (m*Q) >> 22
        const uint32_t sh = 128u - ex;
        const uint64_t u  = (sh < 64u) ? (U0 >> sh) : 0ULL;

        // anchor at level l = 2*chunk: frac(2^l*u), top 32b signed -> [-pi, pi)
        const uint64_t f   = u << lvl;
        const int32_t  ti  = (int32_t)(f >> 32);
        const float    ang = (float)ti * 1.4629180792671596e-9f;  // *2pi/2^32
        const float s0 = __sinf(ang);
        const float c0 = __cosf(ang);

        // one double-angle step for level l+1
        const float t2 = c0 + c0;
        const float c1 = fmaf(t2, c0, -1.0f);
        const float s1 = t2 * s0;

        const bool cls = (iv[i] != 0);
        r[i].x = cls ? e[i].x : s0;
        r[i].y = cls ? e[i].y : c0;
        r[i].z = cls ? e[i].z : s1;
        r[i].w = cls ? e[i].w : c1;
    }

    // ---- phase 4: coalesced float4 stores ----
    #pragma unroll
    for (int i = 0; i < UNROLL; i++)
        out[(size_t)(posBase + i * PSTRIDE) * 16 + chunk] = r[i];
}

extern "C" void kernel_launch(void* const* d_in, const int* in_sizes, int n_in,
                              void* d_out, int out_size)
{
    const float*  values = (const float*)d_in[0];
    const float4* E      = (const float4*)d_in[1];
    const int*    cids   = (const int*)d_in[2];
    const int*    isc    = (const int*)d_in[3];
    float4*       out    = (float4*)d_out;

    const int threads = 256;
    const int blocks  = GSIZE / threads;   // 8192
    pe_kernel<<<blocks, threads>>>(values, E, cids, isc, out);
}